// round 10
// baseline (speedup 1.0000x reference)
#include <cuda_runtime.h>
#include <cuda_bf16.h>
#include <math.h>
#include <stdint.h>

// Problem constants
#define KDIM 128
#define BDIM 16
#define LDIM 8192
#define NF   256            // fine grid (oversampling sigma = 2)
#define WHALF 2.5f          // window half-width (w = 5)
#define BETA  11.5f         // ES beta = 2.30 * w
#define PI_F 3.14159265358979f

#define FSTRIDE 272         // fine-grid row stride (256 + 8 halo + 8 pad)
#define FBATCH  (NF * FSTRIDE)
#define LUTN 1600           // window LUT entries, step 1/512

// Scratch (device globals; no cudaMalloc allowed)
__device__ float    d_phi[65];
__device__ float    d_ctab[256];
__device__ float    d_cos256[256];
__device__ float    d_corner[BDIM];
__device__ float2   d_wlut[LUTN];
__device__ float    d_g[BDIM * KDIM * NF];
__device__ float    d_f[BDIM * FBATCH];
// stage2 A frags (c-circulant on fine grid): [16 mt][8 kt][32 lane][4 regs]
__device__ uint32_t d_A2h[16384];
__device__ uint32_t d_A2l[16384];
// stage2 B frags (g): [16 b][32 vt][8 kt][32 lane][2 regs]
__device__ uint32_t d_Bh[262144];
__device__ uint32_t d_Bl[262144];
// stage1 B frags (C1[n,v] = c[(v-2n)&255]): [8 kt][32 vt][32 lane][2 regs]
__device__ uint32_t d_B1h[16384];
__device__ uint32_t d_B1l[16384];
// stage1 A frags (psi): [16 b][8 mt][8 kt][32 lane][4 regs]
__device__ uint32_t d_Psh[131072];
__device__ uint32_t d_Psl[131072];

__device__ __forceinline__ float es_win(float dist) {
    float z = dist * (1.0f / WHALF);
    float t = 1.0f - z * z;
    if (t <= 0.0f) return 0.0f;
    return expf(BETA * (sqrtf(t) - 1.0f));
}

__device__ __forceinline__ uint32_t packbf(float x, float y) {
    __nv_bfloat162 t = __floats2bfloat162_rn(x, y);
    return *(uint32_t*)&t;
}
__device__ __forceinline__ float bfhi(float x) {
    return __bfloat162float(__float2bfloat16_rn(x));
}

__device__ __forceinline__ void mma_bf16(float4& d, uint4 a, uint2 b) {
    asm("mma.sync.aligned.m16n8k16.row.col.f32.bf16.bf16.f32 "
        "{%0,%1,%2,%3},{%4,%5,%6,%7},{%8,%9},{%0,%1,%2,%3};"
        : "+f"(d.x), "+f"(d.y), "+f"(d.z), "+f"(d.w)
        : "r"(a.x), "r"(a.y), "r"(a.z), "r"(a.w), "r"(b.x), "r"(b.y));
}

// ---------------------------------------------------------------------------
// Prep kernel, grid 89 x 256:
//  blocks 0..64  : Phi_k quadrature    blocks 65..71 : window LUT
//  blocks 72..87 : per-batch corner    block 88      : cos table
// ---------------------------------------------------------------------------
__global__ void prep_kernel(const float* __restrict__ psi) {
    int bid = blockIdx.x;
    int tid = threadIdx.x;

    if (bid < 65) {
        __shared__ float red[256];
        const int NQ = 512;
        float h = (2.0f * WHALF) / NQ;
        float k = (float)bid;
        float acc = 0.0f;
        #pragma unroll
        for (int r = 0; r < 2; r++) {
            int i = tid + r * 256;
            float t = -WHALF + (i + 0.5f) * h;
            acc += es_win(fabsf(t)) * cospif(k * t * (1.0f / 128.0f));
        }
        red[tid] = acc;
        __syncthreads();
        for (int s = 128; s > 0; s >>= 1) {
            if (tid < s) red[tid] += red[tid + s];
            __syncthreads();
        }
        if (tid == 0) d_phi[bid] = red[0] * h;
    } else if (bid < 72) {
        int i = (bid - 65) * 256 + tid;
        if (i < LUTN) {
            float h = 1.0f / 512.0f;
            float v0 = es_win((float)i * h);
            float v1 = es_win((float)(i + 1) * h);
            d_wlut[i] = make_float2(v0, v1 - v0);
        }
    } else if (bid < 88) {
        __shared__ float red[256];
        int b = bid - 72;
        const float* p = psi + b * (KDIM * KDIM);
        float acc = 0.0f;
        for (int idx = tid; idx < KDIM * KDIM; idx += 256) {
            float v = p[idx];
            int par = ((idx >> 7) ^ idx) & 1;
            acc += par ? -v : v;
        }
        red[tid] = acc;
        __syncthreads();
        for (int s = 128; s > 0; s >>= 1) {
            if (tid < s) red[tid] += red[tid + s];
            __syncthreads();
        }
        if (tid == 0) d_corner[b] = red[0];
    } else {
        d_cos256[tid] = cospif((float)tid * (1.0f / 128.0f));
    }
}

// ---------------------------------------------------------------------------
// c-table combine: trig via cos table.
// ---------------------------------------------------------------------------
__global__ void ctab_kernel() {
    __shared__ float sD[65];
    __shared__ float sc[256];
    int tid = threadIdx.x;
    sc[tid] = d_cos256[tid];
    if (tid < 65) sD[tid] = 1.0f / d_phi[tid];
    __syncthreads();
    int d = tid;
    float s = sD[0];
    #pragma unroll 8
    for (int k = 1; k < 64; k++) {
        s = fmaf(2.0f * sD[k], sc[(k * d) & 255], s);
    }
    s = fmaf(sD[64], sc[(64 * d) & 255], s);
    d_ctab[d] = s * (1.0f / 128.0f);
}

// ---------------------------------------------------------------------------
// Fragment generation (batch-independent, from ctab):
//  blocks 0..15 : stage2 A-frags A2[u][m] = c[(u-2m)&255], row-major layout
//  blocks 16..47: stage1 B-frags B1[k][v] = c[(v-2k)&255], col-major layout
// ---------------------------------------------------------------------------
__global__ void fraggen_kernel() {
    int bid = blockIdx.x, tid = threadIdx.x;
    if (bid < 16) {
        int t = bid * 256 + tid;                 // 4096 threads
        int lane = t & 31, kt = (t >> 5) & 7, mt = t >> 8;
        int g = lane >> 2, tg = lane & 3;
        #pragma unroll
        for (int r = 0; r < 4; r++) {
            int u  = mt * 16 + g + (r & 1) * 8;
            int c0 = kt * 16 + 2 * tg + ((r >> 1) & 1) * 8;
            float x0 = d_ctab[(u - 2 * c0) & 255];
            float x1 = d_ctab[(u - 2 * (c0 + 1)) & 255];
            float h0 = bfhi(x0), h1 = bfhi(x1);
            d_A2h[t * 4 + r] = packbf(h0, h1);
            d_A2l[t * 4 + r] = packbf(x0 - h0, x1 - h1);
        }
    } else {
        int t = (bid - 16) * 256 + tid;          // 8192 threads
        int lane = t & 31, vt = (t >> 5) & 31, kt = t >> 10;
        int g = lane >> 2, tg = lane & 3;
        #pragma unroll
        for (int r = 0; r < 2; r++) {
            int k0 = kt * 16 + 2 * tg + r * 8;
            int v  = vt * 8 + g;
            float x0 = d_ctab[(v - 2 * k0) & 255];
            float x1 = d_ctab[(v - 2 * (k0 + 1)) & 255];
            float h0 = bfhi(x0), h1 = bfhi(x1);
            d_B1h[t * 2 + r] = packbf(h0, h1);
            d_B1l[t * 2 + r] = packbf(x0 - h0, x1 - h1);
        }
    }
}

// ---------------------------------------------------------------------------
// psi -> hi/lo bf16 A-fragments [b][mt][kt][lane][4].
// reg r: row = mt*16 + g + (r&1)*8, cols = kt*16 + 2*tg + (r>>1)*8 + {0,1}
// grid: 128 x 256 (32768 threads)
// ---------------------------------------------------------------------------
__global__ void psirepack_kernel(const float* __restrict__ psi) {
    int t = blockIdx.x * 256 + threadIdx.x;
    int lane = t & 31;
    int kt   = (t >> 5) & 7;
    int mt   = (t >> 8) & 7;
    int b    = t >> 11;
    int g = lane >> 2, tg = lane & 3;
    const float* P = psi + b * (KDIM * KDIM);
    #pragma unroll
    for (int r = 0; r < 4; r++) {
        int row = mt * 16 + g + (r & 1) * 8;
        int col = kt * 16 + 2 * tg + ((r >> 1) & 1) * 8;
        float x0 = P[row * KDIM + col];
        float x1 = P[row * KDIM + col + 1];
        float h0 = bfhi(x0), h1 = bfhi(x1);
        d_Psh[t * 4 + r] = packbf(h0, h1);
        d_Psl[t * 4 + r] = packbf(x0 - h0, x1 - h1);
    }
}

// ---------------------------------------------------------------------------
// Stage 1 (tensor): g[b,m,v] = sum_n psi[m,n] * c[(v-2n)&255] via bf16 2-split.
// Block 128 thr = 4 warps (2x2); warp: 1 m-tile x 4 v-tiles.
// grid: (4 v, 4 m, 16 b).
// ---------------------------------------------------------------------------
__global__ void __launch_bounds__(128) stage1_mma_kernel() {
    int b  = blockIdx.z;
    int warp = threadIdx.x >> 5, lane = threadIdx.x & 31;
    int wu = warp >> 1, wv = warp & 1;
    int mt  = blockIdx.y * 2 + wu;           // 0..7
    int vtb = blockIdx.x * 8 + wv * 4;       // 0..28
    int g = lane >> 2, tg = lane & 3;

    float4 d[4];
    #pragma unroll
    for (int j = 0; j < 4; j++) d[j] = make_float4(0.f, 0.f, 0.f, 0.f);

    const uint4* Ah = (const uint4*)d_Psh;
    const uint4* Al = (const uint4*)d_Psl;
    const uint2* Bh = (const uint2*)d_B1h;
    const uint2* Bl = (const uint2*)d_B1l;

    #pragma unroll 2
    for (int kt = 0; kt < 8; kt++) {
        int aidx = ((b * 8 + mt) * 8 + kt) * 32 + lane;
        uint4 ah = Ah[aidx];
        uint4 al = Al[aidx];
        uint2 bh[4], bl[4];
        #pragma unroll
        for (int j = 0; j < 4; j++) {
            int idx = (kt * 32 + vtb + j) * 32 + lane;
            bh[j] = Bh[idx];
            bl[j] = Bl[idx];
        }
        #pragma unroll
        for (int j = 0; j < 4; j++) {
            mma_bf16(d[j], ah, bh[j]);
            mma_bf16(d[j], ah, bl[j]);
            mma_bf16(d[j], al, bh[j]);
        }
    }

    float* G = d_g + b * (KDIM * NF);
    int r0 = mt * 16 + g, r1 = r0 + 8;
    #pragma unroll
    for (int j = 0; j < 4; j++) {
        int v = (vtb + j) * 8 + 2 * tg;
        *(float2*)&G[r0 * NF + v] = make_float2(d[j].x, d[j].y);
        *(float2*)&G[r1 * NF + v] = make_float2(d[j].z, d[j].w);
    }
}

// ---------------------------------------------------------------------------
// Repack: g -> bf16 hi/lo B-fragments [b][vt][kt][lane][2] for stage 2.
// grid: 512 x 256 (131072 threads)
// ---------------------------------------------------------------------------
__global__ void repack_kernel() {
    int t = blockIdx.x * 256 + threadIdx.x;
    int lane = t & 31;
    int kt   = (t >> 5) & 7;
    int vt   = (t >> 8) & 31;
    int b    = t >> 13;
    int g = lane >> 2, tg = lane & 3;
    int v  = vt * 8 + g;
    int m0 = kt * 16 + 2 * tg;
    const float* G = d_g + b * (KDIM * NF);
    float g00 = G[m0 * NF + v];
    float g01 = G[(m0 + 1) * NF + v];
    float g10 = G[(m0 + 8) * NF + v];
    float g11 = G[(m0 + 9) * NF + v];
    float h00 = bfhi(g00), h01 = bfhi(g01), h10 = bfhi(g10), h11 = bfhi(g11);
    d_Bh[2 * t + 0] = packbf(h00, h01);
    d_Bh[2 * t + 1] = packbf(h10, h11);
    d_Bl[2 * t + 0] = packbf(g00 - h00, g01 - h01);
    d_Bl[2 * t + 1] = packbf(g10 - h10, g11 - h11);
}

// ---------------------------------------------------------------------------
// Stage 2 (tensor): f[b,u,v] = sum_m A2[u,m] g[m,v] via bf16 2-split mma.
// Block: 128 threads = 4 warps (2x2); warp: 2 u-tiles x 4 v-tiles.
// grid: (4 v, 4 u, 16 b). Writes padded layout (+4 x offset) and x halo.
// ---------------------------------------------------------------------------
__global__ void __launch_bounds__(128) stage2_mma_kernel() {
    int b   = blockIdx.z;
    int u0t = blockIdx.y * 4;
    int v0t = blockIdx.x * 8;
    int warp = threadIdx.x >> 5, lane = threadIdx.x & 31;
    int wu = warp >> 1, wv = warp & 1;
    int mtb = u0t + wu * 2;
    int vtb = v0t + wv * 4;
    int g = lane >> 2, tg = lane & 3;

    float4 d[2][4];
    #pragma unroll
    for (int i = 0; i < 2; i++)
        #pragma unroll
        for (int j = 0; j < 4; j++)
            d[i][j] = make_float4(0.f, 0.f, 0.f, 0.f);

    const uint4* A2h = (const uint4*)d_A2h;
    const uint4* A2l = (const uint4*)d_A2l;
    const uint2* Bh  = (const uint2*)d_Bh;
    const uint2* Bl  = (const uint2*)d_Bl;

    #pragma unroll 2
    for (int kt = 0; kt < 8; kt++) {
        uint4 ah[2], al[2];
        #pragma unroll
        for (int i = 0; i < 2; i++) {
            int idx = ((mtb + i) * 8 + kt) * 32 + lane;
            ah[i] = A2h[idx];
            al[i] = A2l[idx];
        }
        uint2 bh[4], bl[4];
        #pragma unroll
        for (int j = 0; j < 4; j++) {
            int idx = ((b * 32 + vtb + j) * 8 + kt) * 32 + lane;
            bh[j] = Bh[idx];
            bl[j] = Bl[idx];
        }
        #pragma unroll
        for (int i = 0; i < 2; i++)
            #pragma unroll
            for (int j = 0; j < 4; j++) {
                mma_bf16(d[i][j], ah[i], bh[j]);
                mma_bf16(d[i][j], ah[i], bl[j]);
                mma_bf16(d[i][j], al[i], bh[j]);
            }
    }

    float* F = d_f + b * FBATCH;
    #pragma unroll
    for (int i = 0; i < 2; i++) {
        int r0 = (mtb + i) * 16 + g;
        int r1 = r0 + 8;
        #pragma unroll
        for (int j = 0; j < 4; j++) {
            int v = (vtb + j) * 8 + 2 * tg;
            float2 lo = make_float2(d[i][j].x, d[i][j].y);
            float2 hi = make_float2(d[i][j].z, d[i][j].w);
            *(float2*)&F[r0 * FSTRIDE + v + 4] = lo;
            *(float2*)&F[r1 * FSTRIDE + v + 4] = hi;
            if (v < 4) {
                *(float2*)&F[r0 * FSTRIDE + 260 + v] = lo;
                *(float2*)&F[r1 * FSTRIDE + 260 + v] = hi;
            }
            if (v >= 252) {
                *(float2*)&F[r0 * FSTRIDE + v - 252] = lo;
                *(float2*)&F[r1 * FSTRIDE + v - 252] = hi;
            }
        }
    }
}

// ---------------------------------------------------------------------------
// Interpolation: one thread per point, w=5 ES window via shared LUT.
// ---------------------------------------------------------------------------
__global__ void interp_kernel(const float* __restrict__ x0,
                              const float* __restrict__ y0,
                              float* __restrict__ out) {
    __shared__ float2 slut[LUTN];
    int tid = threadIdx.x;
    for (int i = tid; i < LUTN; i += 256) slut[i] = d_wlut[i];
    __syncthreads();

    int p = blockIdx.x * 256 + tid;
    int b = p >> 13;
    float x = x0[p], y = y0[p];
    float txr = x * (128.0f / PI_F);
    float tyr = y * (128.0f / PI_F);
    float tx = txr + 256.0f;
    float ty = tyr + 256.0f;
    if (tx >= 256.0f) tx -= 256.0f;
    if (ty >= 256.0f) ty -= 256.0f;

    float fx = floorf(tx), fy = floorf(ty);
    int ix0 = (int)fx, iy0 = (int)fy;
    float dx = tx - fx, dy = ty - fy;

    int ic0 = ix0 - 2 + (dx >= 0.5f);
    int xb  = ic0 & ~3;
    int ir0 = iy0 - 2 + (dy >= 0.5f);

    float wx[8];
    #pragma unroll
    for (int j = 0; j < 8; j++) {
        float d  = fabsf(tx - (float)(xb + j));
        float fi = d * 512.0f;
        int idx  = (int)fi;
        float fr = fi - (float)idx;
        if (idx > LUTN - 1) { idx = LUTN - 1; fr = 0.0f; }
        float2 e = slut[idx];
        wx[j] = fmaf(fr, e.y, e.x);
    }
    float wy[5];
    #pragma unroll
    for (int a = 0; a < 5; a++) {
        float d  = fabsf(ty - (float)(ir0 + a));
        float fi = d * 512.0f;
        int idx  = (int)fi;
        float fr = fi - (float)idx;
        if (idx > LUTN - 1) { idx = LUTN - 1; fr = 0.0f; }
        float2 e = slut[idx];
        wy[a] = fmaf(fr, e.y, e.x);
    }

    const float* Fb = d_f + b * FBATCH;
    float acc = 0.0f;
    #pragma unroll
    for (int a = 0; a < 5; a++) {
        int row = (ir0 + a) & 255;
        const float4* rp = (const float4*)(Fb + row * FSTRIDE + xb + 4);
        float4 A = __ldg(rp);
        float4 Bv = __ldg(rp + 1);
        float rs = wx[0] * A.x + wx[1] * A.y + wx[2] * A.z + wx[3] * A.w
                 + wx[4] * Bv.x + wx[5] * Bv.y + wx[6] * Bv.z + wx[7] * Bv.w;
        acc = fmaf(wy[a], rs, acc);
    }

    float corr = d_corner[b] * (1.0f / 16384.0f) *
                 sinpif(0.5f * txr) * sinpif(0.5f * tyr);
    out[p] = acc - corr;
}

// ---------------------------------------------------------------------------
extern "C" void kernel_launch(void* const* d_in, const int* in_sizes, int n_in,
                              void* d_out, int out_size) {
    const float* x0  = (const float*)d_in[0];
    const float* y0  = (const float*)d_in[1];
    const float* psi = (const float*)d_in[2];
    float* out = (float*)d_out;

    prep_kernel<<<89, 256>>>(psi);
    ctab_kernel<<<1, 256>>>();
    fraggen_kernel<<<48, 256>>>();
    psirepack_kernel<<<128, 256>>>(psi);
    stage1_mma_kernel<<<dim3(4, 4, BDIM), 128>>>();
    repack_kernel<<<512, 256>>>();
    stage2_mma_kernel<<<dim3(4, 4, BDIM), 128>>>();
    interp_kernel<<<512, 256>>>(x0, y0, out);
}

// round 11
// speedup vs baseline: 1.7739x; 1.7739x over previous
#include <cuda_runtime.h>
#include <cuda_bf16.h>
#include <math.h>
#include <stdint.h>

// Problem constants
#define KDIM 128
#define BDIM 16
#define LDIM 8192
#define NF   256            // fine grid (oversampling sigma = 2)
#define WHALF 2.5f          // window half-width (w = 5)
#define BETA  11.5f         // ES beta = 2.30 * w
#define PI_F 3.14159265358979f

#define FSTRIDE 272         // fine-grid row stride (256 + 8 halo + 8 pad)
#define FBATCH  (NF * FSTRIDE)
#define LUTN 1600           // window LUT entries, step 1/512

// Scratch (device globals; no cudaMalloc allowed)
__device__ float    d_phi[65];
__device__ float    d_ctab[256];
__device__ float    d_cos256[256];
__device__ float    d_corner[BDIM];
__device__ float2   d_wlut[LUTN];
__device__ float    d_g[BDIM * KDIM * NF];
__device__ float    d_f[BDIM * FBATCH];

__device__ __forceinline__ float es_win(float dist) {
    float z = dist * (1.0f / WHALF);
    float t = 1.0f - z * z;
    if (t <= 0.0f) return 0.0f;
    return expf(BETA * (sqrtf(t) - 1.0f));
}

__device__ __forceinline__ uint32_t packbf(float x, float y) {
    __nv_bfloat162 t = __floats2bfloat162_rn(x, y);
    return *(uint32_t*)&t;
}
__device__ __forceinline__ float bfhi(float x) {
    return __bfloat162float(__float2bfloat16_rn(x));
}

__device__ __forceinline__ void mma_bf16(float4& d, uint4 a, uint2 b) {
    asm("mma.sync.aligned.m16n8k16.row.col.f32.bf16.bf16.f32 "
        "{%0,%1,%2,%3},{%4,%5,%6,%7},{%8,%9},{%0,%1,%2,%3};"
        : "+f"(d.x), "+f"(d.y), "+f"(d.z), "+f"(d.w)
        : "r"(a.x), "r"(a.y), "r"(a.z), "r"(a.w), "r"(b.x), "r"(b.y));
}

// ---------------------------------------------------------------------------
// Prep kernel, grid 89 x 256:
//  blocks 0..64  : Phi_k quadrature    blocks 65..71 : window LUT
//  blocks 72..87 : per-batch corner    block 88      : cos table
// ---------------------------------------------------------------------------
__global__ void prep_kernel(const float* __restrict__ psi) {
    int bid = blockIdx.x;
    int tid = threadIdx.x;

    if (bid < 65) {
        __shared__ float red[256];
        const int NQ = 512;
        float h = (2.0f * WHALF) / NQ;
        float k = (float)bid;
        float acc = 0.0f;
        #pragma unroll
        for (int r = 0; r < 2; r++) {
            int i = tid + r * 256;
            float t = -WHALF + (i + 0.5f) * h;
            acc += es_win(fabsf(t)) * cospif(k * t * (1.0f / 128.0f));
        }
        red[tid] = acc;
        __syncthreads();
        for (int s = 128; s > 0; s >>= 1) {
            if (tid < s) red[tid] += red[tid + s];
            __syncthreads();
        }
        if (tid == 0) d_phi[bid] = red[0] * h;
    } else if (bid < 72) {
        int i = (bid - 65) * 256 + tid;
        if (i < LUTN) {
            float h = 1.0f / 512.0f;
            float v0 = es_win((float)i * h);
            float v1 = es_win((float)(i + 1) * h);
            d_wlut[i] = make_float2(v0, v1 - v0);
        }
    } else if (bid < 88) {
        __shared__ float red[256];
        int b = bid - 72;
        const float* p = psi + b * (KDIM * KDIM);
        float acc = 0.0f;
        for (int idx = tid; idx < KDIM * KDIM; idx += 256) {
            float v = p[idx];
            int par = ((idx >> 7) ^ idx) & 1;
            acc += par ? -v : v;
        }
        red[tid] = acc;
        __syncthreads();
        for (int s = 128; s > 0; s >>= 1) {
            if (tid < s) red[tid] += red[tid + s];
            __syncthreads();
        }
        if (tid == 0) d_corner[b] = red[0];
    } else {
        d_cos256[tid] = cospif((float)tid * (1.0f / 128.0f));
    }
}

// ---------------------------------------------------------------------------
// c-table combine: trig via cos table.
// ---------------------------------------------------------------------------
__global__ void ctab_kernel() {
    __shared__ float sD[65];
    __shared__ float sc[256];
    int tid = threadIdx.x;
    sc[tid] = d_cos256[tid];
    if (tid < 65) sD[tid] = 1.0f / d_phi[tid];
    __syncthreads();
    int d = tid;
    float s = sD[0];
    #pragma unroll 8
    for (int k = 1; k < 64; k++) {
        s = fmaf(2.0f * sD[k], sc[(k * d) & 255], s);
    }
    s = fmaf(sD[64], sc[(64 * d) & 255], s);
    d_ctab[d] = s * (1.0f / 128.0f);
}

// ---------------------------------------------------------------------------
// Stage 1 (tensor, self-contained):
//   g[b,m,v] = sum_n psi[b,m,n] * c[(v-2n)&255]
// Block 128 thr = 4 warps (2x2). Block tile: 32 m x 64 v, full K=128.
// psi slice staged to smem ONCE (bf16x2 hi/lo pairs over n, stride 68 words:
// conflict-free a-frag LDS). c-operand from 256-entry cpair smem table.
// grid: (4 v, 4 m, 16 b)
// ---------------------------------------------------------------------------
__global__ void __launch_bounds__(128) stage1_mma_kernel(const float* __restrict__ psi) {
    __shared__ uint32_t cph[256], cpl[256];
    __shared__ uint32_t Ah[32][68], Al[32][68];   // [m-local][n2], n2 = n/2
    int b   = blockIdx.z;
    int m0b = blockIdx.y * 32;
    int tid = threadIdx.x;

    // cpair: {c[i], c[(i-2)&255]} split hi/lo
    for (int i = tid; i < 256; i += 128) {
        float x = d_ctab[i], y = d_ctab[(i + 254) & 255];
        float hx = bfhi(x), hy = bfhi(y);
        cph[i] = packbf(hx, hy);
        cpl[i] = packbf(x - hx, y - hy);
    }
    // stage psi slice [m0b..m0b+32) x [0..128)
    const float* P = psi + b * (KDIM * KDIM) + m0b * KDIM;
    #pragma unroll
    for (int i = 0; i < 8; i++) {
        int u = tid + i * 128;                 // 1024 float4 units
        int row = u >> 5, n4 = (u & 31) * 4;
        float4 a = *(const float4*)&P[row * KDIM + n4];
        float h0 = bfhi(a.x), h1 = bfhi(a.y), h2 = bfhi(a.z), h3 = bfhi(a.w);
        int n2 = n4 >> 1;
        Ah[row][n2]     = packbf(h0, h1);
        Al[row][n2]     = packbf(a.x - h0, a.y - h1);
        Ah[row][n2 + 1] = packbf(h2, h3);
        Al[row][n2 + 1] = packbf(a.z - h2, a.w - h3);
    }
    __syncthreads();

    int warp = tid >> 5, lane = tid & 31;
    int wu = warp >> 1, wv = warp & 1;
    int g = lane >> 2, tg = lane & 3;
    int vtb = blockIdx.x * 8 + wv * 4;         // v-tiles of 8

    float4 d[4];
    #pragma unroll
    for (int j = 0; j < 4; j++) d[j] = make_float4(0.f, 0.f, 0.f, 0.f);

    #pragma unroll
    for (int kt = 0; kt < 8; kt++) {
        int rl0 = wu * 16 + g;
        int n20 = kt * 8 + tg;
        uint4 ah, al;
        ah.x = Ah[rl0][n20];         al.x = Al[rl0][n20];
        ah.y = Ah[rl0 + 8][n20];     al.y = Al[rl0 + 8][n20];
        ah.z = Ah[rl0][n20 + 4];     al.z = Al[rl0][n20 + 4];
        ah.w = Ah[rl0 + 8][n20 + 4]; al.w = Al[rl0 + 8][n20 + 4];
        int k0 = kt * 16 + 2 * tg;
        #pragma unroll
        for (int j = 0; j < 4; j++) {
            int v = (vtb + j) * 8 + g;
            uint2 bh, bl;
            int i0 = (v - 2 * k0 + 512) & 255;
            int i1 = (v - 2 * (k0 + 8) + 512) & 255;
            bh.x = cph[i0];  bl.x = cpl[i0];
            bh.y = cph[i1];  bl.y = cpl[i1];
            mma_bf16(d[j], ah, bh);
            mma_bf16(d[j], ah, bl);
            mma_bf16(d[j], al, bh);
        }
    }

    float* G = d_g + b * (KDIM * NF);
    int r0 = m0b + wu * 16 + g, r1 = r0 + 8;
    #pragma unroll
    for (int j = 0; j < 4; j++) {
        int v = (vtb + j) * 8 + 2 * tg;
        *(float2*)&G[r0 * NF + v] = make_float2(d[j].x, d[j].y);
        *(float2*)&G[r1 * NF + v] = make_float2(d[j].z, d[j].w);
    }
}

// ---------------------------------------------------------------------------
// Stage 2 (tensor, self-contained):
//   f[b,u,v] = sum_m c[(u-2m)&255] * g[b,m,v]
// Block 128 thr = 4 warps (2x2). Block tile: 64 u x 64 v, full K=128.
// g slice staged to smem ONCE (bf16x2 hi/lo pairs over m, stride 72 words:
// conflict-free b-frag LDS). A-operand from cpair smem table.
// grid: (4 v, 4 u, 16 b). Writes padded layout (+4 x offset) and x halo.
// ---------------------------------------------------------------------------
__global__ void __launch_bounds__(128) stage2_mma_kernel() {
    __shared__ uint32_t cph[256], cpl[256];
    __shared__ uint32_t Bh[64][72], Bl[64][72];   // [m2][v-local], m2 = m/2
    int b   = blockIdx.z;
    int u0b = blockIdx.y * 64;
    int v0  = blockIdx.x * 64;
    int tid = threadIdx.x;

    for (int i = tid; i < 256; i += 128) {
        float x = d_ctab[i], y = d_ctab[(i + 254) & 255];
        float hx = bfhi(x), hy = bfhi(y);
        cph[i] = packbf(hx, hy);
        cpl[i] = packbf(x - hx, y - hy);
    }
    // stage g slice [0..128) m x [v0..v0+64): pairs over m
    const float* G = d_g + b * (KDIM * NF);
    #pragma unroll
    for (int i = 0; i < 8; i++) {
        int u = tid + i * 128;                 // 1024 float4 units
        int m2 = u >> 4, v4 = (u & 15) * 4;
        float4 ra = *(const float4*)&G[(2 * m2) * NF + v0 + v4];
        float4 rb = *(const float4*)&G[(2 * m2 + 1) * NF + v0 + v4];
        float ha, hb;
        ha = bfhi(ra.x); hb = bfhi(rb.x);
        Bh[m2][v4]     = packbf(ha, hb);
        Bl[m2][v4]     = packbf(ra.x - ha, rb.x - hb);
        ha = bfhi(ra.y); hb = bfhi(rb.y);
        Bh[m2][v4 + 1] = packbf(ha, hb);
        Bl[m2][v4 + 1] = packbf(ra.y - ha, rb.y - hb);
        ha = bfhi(ra.z); hb = bfhi(rb.z);
        Bh[m2][v4 + 2] = packbf(ha, hb);
        Bl[m2][v4 + 2] = packbf(ra.z - ha, rb.z - hb);
        ha = bfhi(ra.w); hb = bfhi(rb.w);
        Bh[m2][v4 + 3] = packbf(ha, hb);
        Bl[m2][v4 + 3] = packbf(ra.w - ha, rb.w - hb);
    }
    __syncthreads();

    int warp = tid >> 5, lane = tid & 31;
    int wu = warp >> 1, wv = warp & 1;
    int g = lane >> 2, tg = lane & 3;
    int mtb = wu * 2;                           // local u-tiles (of 16): 0 or 2
    int vtb = wv * 4;                           // local v-tiles (of 8)

    float4 d[2][4];
    #pragma unroll
    for (int i = 0; i < 2; i++)
        #pragma unroll
        for (int j = 0; j < 4; j++)
            d[i][j] = make_float4(0.f, 0.f, 0.f, 0.f);

    #pragma unroll
    for (int kt = 0; kt < 8; kt++) {
        uint4 ah[2], al[2];
        int m00 = kt * 16 + 2 * tg;
        #pragma unroll
        for (int i = 0; i < 2; i++) {
            int ug0 = u0b + (mtb + i) * 16 + g;
            int ia0 = (ug0 - 2 * m00 + 512) & 255;
            int ia1 = (ug0 + 8 - 2 * m00 + 512) & 255;
            int ia2 = (ug0 - 2 * (m00 + 8) + 512) & 255;
            int ia3 = (ug0 + 8 - 2 * (m00 + 8) + 512) & 255;
            ah[i].x = cph[ia0];  al[i].x = cpl[ia0];
            ah[i].y = cph[ia1];  al[i].y = cpl[ia1];
            ah[i].z = cph[ia2];  al[i].z = cpl[ia2];
            ah[i].w = cph[ia3];  al[i].w = cpl[ia3];
        }
        int m20 = kt * 8 + tg;
        uint2 bh[4], bl[4];
        #pragma unroll
        for (int j = 0; j < 4; j++) {
            int vl = (vtb + j) * 8 + g;
            bh[j].x = Bh[m20][vl];      bl[j].x = Bl[m20][vl];
            bh[j].y = Bh[m20 + 4][vl];  bl[j].y = Bl[m20 + 4][vl];
        }
        #pragma unroll
        for (int i = 0; i < 2; i++)
            #pragma unroll
            for (int j = 0; j < 4; j++) {
                mma_bf16(d[i][j], ah[i], bh[j]);
                mma_bf16(d[i][j], ah[i], bl[j]);
                mma_bf16(d[i][j], al[i], bh[j]);
            }
    }

    float* F = d_f + b * FBATCH;
    #pragma unroll
    for (int i = 0; i < 2; i++) {
        int r0 = u0b + (mtb + i) * 16 + g;
        int r1 = r0 + 8;
        #pragma unroll
        for (int j = 0; j < 4; j++) {
            int v = v0 + (vtb + j) * 8 + 2 * tg;   // even, in [0,256)
            float2 lo = make_float2(d[i][j].x, d[i][j].y);
            float2 hi = make_float2(d[i][j].z, d[i][j].w);
            *(float2*)&F[r0 * FSTRIDE + v + 4] = lo;
            *(float2*)&F[r1 * FSTRIDE + v + 4] = hi;
            if (v < 4) {
                *(float2*)&F[r0 * FSTRIDE + 260 + v] = lo;
                *(float2*)&F[r1 * FSTRIDE + 260 + v] = hi;
            }
            if (v >= 252) {
                *(float2*)&F[r0 * FSTRIDE + v - 252] = lo;
                *(float2*)&F[r1 * FSTRIDE + v - 252] = hi;
            }
        }
    }
}

// ---------------------------------------------------------------------------
// Interpolation: one thread per point, w=5 ES window via shared LUT.
// ---------------------------------------------------------------------------
__global__ void interp_kernel(const float* __restrict__ x0,
                              const float* __restrict__ y0,
                              float* __restrict__ out) {
    __shared__ float2 slut[LUTN];
    int tid = threadIdx.x;
    for (int i = tid; i < LUTN; i += 256) slut[i] = d_wlut[i];
    __syncthreads();

    int p = blockIdx.x * 256 + tid;
    int b = p >> 13;
    float x = x0[p], y = y0[p];
    float txr = x * (128.0f / PI_F);
    float tyr = y * (128.0f / PI_F);
    float tx = txr + 256.0f;
    float ty = tyr + 256.0f;
    if (tx >= 256.0f) tx -= 256.0f;
    if (ty >= 256.0f) ty -= 256.0f;

    float fx = floorf(tx), fy = floorf(ty);
    int ix0 = (int)fx, iy0 = (int)fy;
    float dx = tx - fx, dy = ty - fy;

    int ic0 = ix0 - 2 + (dx >= 0.5f);
    int xb  = ic0 & ~3;
    int ir0 = iy0 - 2 + (dy >= 0.5f);

    float wx[8];
    #pragma unroll
    for (int j = 0; j < 8; j++) {
        float d  = fabsf(tx - (float)(xb + j));
        float fi = d * 512.0f;
        int idx  = (int)fi;
        float fr = fi - (float)idx;
        if (idx > LUTN - 1) { idx = LUTN - 1; fr = 0.0f; }
        float2 e = slut[idx];
        wx[j] = fmaf(fr, e.y, e.x);
    }
    float wy[5];
    #pragma unroll
    for (int a = 0; a < 5; a++) {
        float d  = fabsf(ty - (float)(ir0 + a));
        float fi = d * 512.0f;
        int idx  = (int)fi;
        float fr = fi - (float)idx;
        if (idx > LUTN - 1) { idx = LUTN - 1; fr = 0.0f; }
        float2 e = slut[idx];
        wy[a] = fmaf(fr, e.y, e.x);
    }

    const float* Fb = d_f + b * FBATCH;
    float acc = 0.0f;
    #pragma unroll
    for (int a = 0; a < 5; a++) {
        int row = (ir0 + a) & 255;
        const float4* rp = (const float4*)(Fb + row * FSTRIDE + xb + 4);
        float4 A = __ldg(rp);
        float4 Bv = __ldg(rp + 1);
        float rs = wx[0] * A.x + wx[1] * A.y + wx[2] * A.z + wx[3] * A.w
                 + wx[4] * Bv.x + wx[5] * Bv.y + wx[6] * Bv.z + wx[7] * Bv.w;
        acc = fmaf(wy[a], rs, acc);
    }

    float corr = d_corner[b] * (1.0f / 16384.0f) *
                 sinpif(0.5f * txr) * sinpif(0.5f * tyr);
    out[p] = acc - corr;
}

// ---------------------------------------------------------------------------
extern "C" void kernel_launch(void* const* d_in, const int* in_sizes, int n_in,
                              void* d_out, int out_size) {
    const float* x0  = (const float*)d_in[0];
    const float* y0  = (const float*)d_in[1];
    const float* psi = (const float*)d_in[2];
    float* out = (float*)d_out;

    prep_kernel<<<89, 256>>>(psi);
    ctab_kernel<<<1, 256>>>();
    stage1_mma_kernel<<<dim3(4, 4, BDIM), 128>>>(psi);
    stage2_mma_kernel<<<dim3(4, 4, BDIM), 128>>>();
    interp_kernel<<<512, 256>>>(x0, y0, out);
}

// round 12
// speedup vs baseline: 1.7856x; 1.0066x over previous
#include <cuda_runtime.h>
#include <cuda_bf16.h>
#include <math.h>
#include <stdint.h>

// Problem constants
#define KDIM 128
#define BDIM 16
#define LDIM 8192
#define NF   256            // fine grid (oversampling sigma = 2)
#define WHALF 2.5f          // window half-width (w = 5)
#define BETA  11.5f         // ES beta = 2.30 * w
#define PI_F 3.14159265358979f

#define FSTRIDE 272         // fine-grid row stride (256 + 8 halo + 8 pad)
#define FBATCH  (NF * FSTRIDE)
#define LUTN 1600           // window LUT entries, step 1/512

// Scratch (device globals; no cudaMalloc allowed)
__device__ float    d_phi[65];
__device__ float    d_ctab[256];
__device__ float    d_cos256[256];
__device__ float    d_corner[BDIM];
__device__ float2   d_wlut[LUTN];
__device__ float    d_g[BDIM * KDIM * NF];
__device__ float    d_f[BDIM * FBATCH];

__device__ __forceinline__ float es_win(float dist) {
    float z = dist * (1.0f / WHALF);
    float t = 1.0f - z * z;
    if (t <= 0.0f) return 0.0f;
    return expf(BETA * (sqrtf(t) - 1.0f));
}

__device__ __forceinline__ uint32_t packbf(float x, float y) {
    __nv_bfloat162 t = __floats2bfloat162_rn(x, y);
    return *(uint32_t*)&t;
}
__device__ __forceinline__ float bfhi(float x) {
    return __bfloat162float(__float2bfloat16_rn(x));
}

__device__ __forceinline__ void mma_bf16(float4& d, uint4 a, uint2 b) {
    asm("mma.sync.aligned.m16n8k16.row.col.f32.bf16.bf16.f32 "
        "{%0,%1,%2,%3},{%4,%5,%6,%7},{%8,%9},{%0,%1,%2,%3};"
        : "+f"(d.x), "+f"(d.y), "+f"(d.z), "+f"(d.w)
        : "r"(a.x), "r"(a.y), "r"(a.z), "r"(a.w), "r"(b.x), "r"(b.y));
}

// ---------------------------------------------------------------------------
// Prep kernel, grid 89 x 256:
//  blocks 0..64  : Phi_k quadrature    blocks 65..71 : window LUT
//  blocks 72..87 : per-batch corner    block 88      : cos table
// ---------------------------------------------------------------------------
__global__ void prep_kernel(const float* __restrict__ psi) {
    int bid = blockIdx.x;
    int tid = threadIdx.x;

    if (bid < 65) {
        __shared__ float red[256];
        const int NQ = 512;
        float h = (2.0f * WHALF) / NQ;
        float k = (float)bid;
        float acc = 0.0f;
        #pragma unroll
        for (int r = 0; r < 2; r++) {
            int i = tid + r * 256;
            float t = -WHALF + (i + 0.5f) * h;
            acc += es_win(fabsf(t)) * cospif(k * t * (1.0f / 128.0f));
        }
        red[tid] = acc;
        __syncthreads();
        for (int s = 128; s > 0; s >>= 1) {
            if (tid < s) red[tid] += red[tid + s];
            __syncthreads();
        }
        if (tid == 0) d_phi[bid] = red[0] * h;
    } else if (bid < 72) {
        int i = (bid - 65) * 256 + tid;
        if (i < LUTN) {
            float h = 1.0f / 512.0f;
            float v0 = es_win((float)i * h);
            float v1 = es_win((float)(i + 1) * h);
            d_wlut[i] = make_float2(v0, v1 - v0);
        }
    } else if (bid < 88) {
        __shared__ float red[256];
        int b = bid - 72;
        const float* p = psi + b * (KDIM * KDIM);
        float acc = 0.0f;
        for (int idx = tid; idx < KDIM * KDIM; idx += 256) {
            float v = p[idx];
            int par = ((idx >> 7) ^ idx) & 1;
            acc += par ? -v : v;
        }
        red[tid] = acc;
        __syncthreads();
        for (int s = 128; s > 0; s >>= 1) {
            if (tid < s) red[tid] += red[tid + s];
            __syncthreads();
        }
        if (tid == 0) d_corner[b] = red[0];
    } else {
        d_cos256[tid] = cospif((float)tid * (1.0f / 128.0f));
    }
}

// ---------------------------------------------------------------------------
// c-table combine: trig via cos table.
// ---------------------------------------------------------------------------
__global__ void ctab_kernel() {
    __shared__ float sD[65];
    __shared__ float sc[256];
    int tid = threadIdx.x;
    sc[tid] = d_cos256[tid];
    if (tid < 65) sD[tid] = 1.0f / d_phi[tid];
    __syncthreads();
    int d = tid;
    float s = sD[0];
    #pragma unroll 8
    for (int k = 1; k < 64; k++) {
        s = fmaf(2.0f * sD[k], sc[(k * d) & 255], s);
    }
    s = fmaf(sD[64], sc[(64 * d) & 255], s);
    d_ctab[d] = s * (1.0f / 128.0f);
}

// ---------------------------------------------------------------------------
// Stage 1 (tensor): g[b,m,v] = sum_n psi[b,m,n] * c[(v-2n)&255]
// Block 256 thr = 8 warps. Block tile: 32 m x 64 v, full K=128.
// Warp: 1 m-tile (16) x 2 v-tiles (16). psi slice staged once (hi/lo bf16x2).
// grid: (4 v, 4 m, 16 b)
// ---------------------------------------------------------------------------
__global__ void __launch_bounds__(256) stage1_mma_kernel(const float* __restrict__ psi) {
    __shared__ uint32_t cph[256], cpl[256];
    __shared__ uint32_t Ah[32][68], Al[32][68];   // [m-local][n2], n2 = n/2
    int b   = blockIdx.z;
    int m0b = blockIdx.y * 32;
    int tid = threadIdx.x;

    // cpair: {c[i], c[(i-2)&255]} split hi/lo
    {
        int i = tid;
        float x = d_ctab[i], y = d_ctab[(i + 254) & 255];
        float hx = bfhi(x), hy = bfhi(y);
        cph[i] = packbf(hx, hy);
        cpl[i] = packbf(x - hx, y - hy);
    }
    // stage psi slice [m0b..m0b+32) x [0..128)
    const float* P = psi + b * (KDIM * KDIM) + m0b * KDIM;
    #pragma unroll
    for (int i = 0; i < 4; i++) {
        int u = tid + i * 256;                 // 1024 float4 units
        int row = u >> 5, n4 = (u & 31) * 4;
        float4 a = *(const float4*)&P[row * KDIM + n4];
        float h0 = bfhi(a.x), h1 = bfhi(a.y), h2 = bfhi(a.z), h3 = bfhi(a.w);
        int n2 = n4 >> 1;
        Ah[row][n2]     = packbf(h0, h1);
        Al[row][n2]     = packbf(a.x - h0, a.y - h1);
        Ah[row][n2 + 1] = packbf(h2, h3);
        Al[row][n2 + 1] = packbf(a.z - h2, a.w - h3);
    }
    __syncthreads();

    int warp = tid >> 5, lane = tid & 31;
    int wu = warp >> 2, wv = warp & 3;        // wu: 0..1 (m-tile), wv: 0..3
    int g = lane >> 2, tg = lane & 3;
    int vtb = blockIdx.x * 8 + wv * 2;        // 2 v-tiles (of 8) per warp

    float4 d[2];
    #pragma unroll
    for (int j = 0; j < 2; j++) d[j] = make_float4(0.f, 0.f, 0.f, 0.f);

    #pragma unroll
    for (int kt = 0; kt < 8; kt++) {
        int rl0 = wu * 16 + g;
        int n20 = kt * 8 + tg;
        uint4 ah, al;
        ah.x = Ah[rl0][n20];         al.x = Al[rl0][n20];
        ah.y = Ah[rl0 + 8][n20];     al.y = Al[rl0 + 8][n20];
        ah.z = Ah[rl0][n20 + 4];     al.z = Al[rl0][n20 + 4];
        ah.w = Ah[rl0 + 8][n20 + 4]; al.w = Al[rl0 + 8][n20 + 4];
        int k0 = kt * 16 + 2 * tg;
        #pragma unroll
        for (int j = 0; j < 2; j++) {
            int v = (vtb + j) * 8 + g;
            uint2 bh, bl;
            int i0 = (v - 2 * k0 + 512) & 255;
            int i1 = (v - 2 * (k0 + 8) + 512) & 255;
            bh.x = cph[i0];  bl.x = cpl[i0];
            bh.y = cph[i1];  bl.y = cpl[i1];
            mma_bf16(d[j], ah, bh);
            mma_bf16(d[j], ah, bl);
            mma_bf16(d[j], al, bh);
        }
    }

    float* G = d_g + b * (KDIM * NF);
    int r0 = m0b + wu * 16 + g, r1 = r0 + 8;
    #pragma unroll
    for (int j = 0; j < 2; j++) {
        int v = (vtb + j) * 8 + 2 * tg;
        *(float2*)&G[r0 * NF + v] = make_float2(d[j].x, d[j].y);
        *(float2*)&G[r1 * NF + v] = make_float2(d[j].z, d[j].w);
    }
}

// ---------------------------------------------------------------------------
// Stage 2 (tensor): f[b,u,v] = sum_m c[(u-2m)&255] * g[b,m,v]
// Block 256 thr = 8 warps. Block tile: 64 u x 64 v, full K=128.
// Warp: 1 u-tile (16) x 4 v-tiles (32). g slice staged once (hi/lo bf16x2).
// grid: (4 v, 4 u, 16 b). Writes padded layout (+4 x offset) and x halo.
// ---------------------------------------------------------------------------
__global__ void __launch_bounds__(256) stage2_mma_kernel() {
    __shared__ uint32_t cph[256], cpl[256];
    __shared__ uint32_t Bh[64][72], Bl[64][72];   // [m2][v-local], m2 = m/2
    int b   = blockIdx.z;
    int u0b = blockIdx.y * 64;
    int v0  = blockIdx.x * 64;
    int tid = threadIdx.x;

    {
        int i = tid;
        float x = d_ctab[i], y = d_ctab[(i + 254) & 255];
        float hx = bfhi(x), hy = bfhi(y);
        cph[i] = packbf(hx, hy);
        cpl[i] = packbf(x - hx, y - hy);
    }
    // stage g slice [0..128) m x [v0..v0+64): pairs over m
    const float* G = d_g + b * (KDIM * NF);
    #pragma unroll
    for (int i = 0; i < 4; i++) {
        int u = tid + i * 256;                 // 1024 float4 units
        int m2 = u >> 4, v4 = (u & 15) * 4;
        float4 ra = *(const float4*)&G[(2 * m2) * NF + v0 + v4];
        float4 rb = *(const float4*)&G[(2 * m2 + 1) * NF + v0 + v4];
        float ha, hb;
        ha = bfhi(ra.x); hb = bfhi(rb.x);
        Bh[m2][v4]     = packbf(ha, hb);
        Bl[m2][v4]     = packbf(ra.x - ha, rb.x - hb);
        ha = bfhi(ra.y); hb = bfhi(rb.y);
        Bh[m2][v4 + 1] = packbf(ha, hb);
        Bl[m2][v4 + 1] = packbf(ra.y - ha, rb.y - hb);
        ha = bfhi(ra.z); hb = bfhi(rb.z);
        Bh[m2][v4 + 2] = packbf(ha, hb);
        Bl[m2][v4 + 2] = packbf(ra.z - ha, rb.z - hb);
        ha = bfhi(ra.w); hb = bfhi(rb.w);
        Bh[m2][v4 + 3] = packbf(ha, hb);
        Bl[m2][v4 + 3] = packbf(ra.w - ha, rb.w - hb);
    }
    __syncthreads();

    int warp = tid >> 5, lane = tid & 31;
    int wu = warp >> 1, wv = warp & 1;        // wu: 0..3 (u-tile), wv: 0..1
    int g = lane >> 2, tg = lane & 3;
    int mtb = wu;                              // local u-tile (of 16)
    int vtb = wv * 4;                          // 4 v-tiles (of 8) per warp

    float4 d[4];
    #pragma unroll
    for (int j = 0; j < 4; j++) d[j] = make_float4(0.f, 0.f, 0.f, 0.f);

    #pragma unroll
    for (int kt = 0; kt < 8; kt++) {
        uint4 ah, al;
        int m00 = kt * 16 + 2 * tg;
        {
            int ug0 = u0b + mtb * 16 + g;
            int ia0 = (ug0 - 2 * m00 + 512) & 255;
            int ia1 = (ug0 + 8 - 2 * m00 + 512) & 255;
            int ia2 = (ug0 - 2 * (m00 + 8) + 512) & 255;
            int ia3 = (ug0 + 8 - 2 * (m00 + 8) + 512) & 255;
            ah.x = cph[ia0];  al.x = cpl[ia0];
            ah.y = cph[ia1];  al.y = cpl[ia1];
            ah.z = cph[ia2];  al.z = cpl[ia2];
            ah.w = cph[ia3];  al.w = cpl[ia3];
        }
        int m20 = kt * 8 + tg;
        #pragma unroll
        for (int j = 0; j < 4; j++) {
            int vl = (vtb + j) * 8 + g;
            uint2 bh, bl;
            bh.x = Bh[m20][vl];      bl.x = Bl[m20][vl];
            bh.y = Bh[m20 + 4][vl];  bl.y = Bl[m20 + 4][vl];
            mma_bf16(d[j], ah, bh);
            mma_bf16(d[j], ah, bl);
            mma_bf16(d[j], al, bh);
        }
    }

    float* F = d_f + b * FBATCH;
    int r0 = u0b + mtb * 16 + g;
    int r1 = r0 + 8;
    #pragma unroll
    for (int j = 0; j < 4; j++) {
        int v = v0 + (vtb + j) * 8 + 2 * tg;   // even, in [0,256)
        float2 lo = make_float2(d[j].x, d[j].y);
        float2 hi = make_float2(d[j].z, d[j].w);
        *(float2*)&F[r0 * FSTRIDE + v + 4] = lo;
        *(float2*)&F[r1 * FSTRIDE + v + 4] = hi;
        if (v < 4) {
            *(float2*)&F[r0 * FSTRIDE + 260 + v] = lo;
            *(float2*)&F[r1 * FSTRIDE + 260 + v] = hi;
        }
        if (v >= 252) {
            *(float2*)&F[r0 * FSTRIDE + v - 252] = lo;
            *(float2*)&F[r1 * FSTRIDE + v - 252] = hi;
        }
    }
}

// ---------------------------------------------------------------------------
// Interpolation: one thread per point, w=5 ES window via shared LUT.
// ---------------------------------------------------------------------------
__global__ void interp_kernel(const float* __restrict__ x0,
                              const float* __restrict__ y0,
                              float* __restrict__ out) {
    __shared__ float2 slut[LUTN];
    int tid = threadIdx.x;
    for (int i = tid; i < LUTN; i += 256) slut[i] = d_wlut[i];
    __syncthreads();

    int p = blockIdx.x * 256 + tid;
    int b = p >> 13;
    float x = x0[p], y = y0[p];
    float txr = x * (128.0f / PI_F);
    float tyr = y * (128.0f / PI_F);
    float tx = txr + 256.0f;
    float ty = tyr + 256.0f;
    if (tx >= 256.0f) tx -= 256.0f;
    if (ty >= 256.0f) ty -= 256.0f;

    float fx = floorf(tx), fy = floorf(ty);
    int ix0 = (int)fx, iy0 = (int)fy;
    float dx = tx - fx, dy = ty - fy;

    int ic0 = ix0 - 2 + (dx >= 0.5f);
    int xb  = ic0 & ~3;
    int ir0 = iy0 - 2 + (dy >= 0.5f);

    float wx[8];
    #pragma unroll
    for (int j = 0; j < 8; j++) {
        float d  = fabsf(tx - (float)(xb + j));
        float fi = d * 512.0f;
        int idx  = (int)fi;
        float fr = fi - (float)idx;
        if (idx > LUTN - 1) { idx = LUTN - 1; fr = 0.0f; }
        float2 e = slut[idx];
        wx[j] = fmaf(fr, e.y, e.x);
    }
    float wy[5];
    #pragma unroll
    for (int a = 0; a < 5; a++) {
        float d  = fabsf(ty - (float)(ir0 + a));
        float fi = d * 512.0f;
        int idx  = (int)fi;
        float fr = fi - (float)idx;
        if (idx > LUTN - 1) { idx = LUTN - 1; fr = 0.0f; }
        float2 e = slut[idx];
        wy[a] = fmaf(fr, e.y, e.x);
    }

    const float* Fb = d_f + b * FBATCH;
    float acc = 0.0f;
    #pragma unroll
    for (int a = 0; a < 5; a++) {
        int row = (ir0 + a) & 255;
        const float4* rp = (const float4*)(Fb + row * FSTRIDE + xb + 4);
        float4 A = __ldg(rp);
        float4 Bv = __ldg(rp + 1);
        float rs = wx[0] * A.x + wx[1] * A.y + wx[2] * A.z + wx[3] * A.w
                 + wx[4] * Bv.x + wx[5] * Bv.y + wx[6] * Bv.z + wx[7] * Bv.w;
        acc = fmaf(wy[a], rs, acc);
    }

    float corr = d_corner[b] * (1.0f / 16384.0f) *
                 sinpif(0.5f * txr) * sinpif(0.5f * tyr);
    out[p] = acc - corr;
}

// ---------------------------------------------------------------------------
extern "C" void kernel_launch(void* const* d_in, const int* in_sizes, int n_in,
                              void* d_out, int out_size) {
    const float* x0  = (const float*)d_in[0];
    const float* y0  = (const float*)d_in[1];
    const float* psi = (const float*)d_in[2];
    float* out = (float*)d_out;

    prep_kernel<<<89, 256>>>(psi);
    ctab_kernel<<<1, 256>>>();
    stage1_mma_kernel<<<dim3(4, 4, BDIM), 256>>>(psi);
    stage2_mma_kernel<<<dim3(4, 4, BDIM), 256>>>();
    interp_kernel<<<512, 256>>>(x0, y0, out);
}